// round 6
// baseline (speedup 1.0000x reference)
#include <cuda_runtime.h>
#include <math.h>
#include <stdint.h>

// ---------------------------------------------------------------------------
// Encoder_51582557225690 : 8-layer beacon/forget memory transformer.
// R6: k-interleaved smem (float2 fragment LDS, halves inner-loop issue),
// masked-tile skipping in qk/softmax/PV (attention work -> ~60%).
// L=8 D=1024 H=16 HD=64 S=1024 M=128 F=2048 B=1
// ---------------------------------------------------------------------------

#define DD    1024
#define HH    16
#define HDIM  64
#define SS    1024
#define MM    128
#define LL    8
#define FF    2048
#define NCAT  1280
#define NKR   1408
#define NPOS  1280

// ------------------------- device scratch (no allocs) ----------------------
__device__ float g_cat [NCAT * DD];
__device__ float g_x   [NCAT * DD];
__device__ float g_q   [NCAT * DD];
__device__ float g_k   [NKR  * DD];
__device__ float g_v   [NKR  * DD];
__device__ float g_attn[NCAT * DD];
__device__ float g_ffg [NCAT * FF];
__device__ float g_ffu [NCAT * FF];
__device__ float g_scores[(size_t)HH * NCAT * NKR];   // 115 MB BSS scratch
__device__ float g_cos [NPOS * 32];
__device__ float g_sin [NPOS * 32];

// ------------------------------- tf32 helpers ------------------------------
__device__ __forceinline__ float tf32r(float x) {
    uint32_t u;
    asm("cvt.rna.tf32.f32 %0, %1;" : "=r"(u) : "f"(x));
    return __uint_as_float(u);
}
__device__ __forceinline__ void mma8(float* c, const uint32_t* a, const uint32_t* b) {
    asm volatile(
        "mma.sync.aligned.m16n8k8.row.col.f32.tf32.tf32.f32 "
        "{%0,%1,%2,%3},{%4,%5,%6,%7},{%8,%9},{%0,%1,%2,%3};"
        : "+f"(c[0]), "+f"(c[1]), "+f"(c[2]), "+f"(c[3])
        : "r"(a[0]), "r"(a[1]), "r"(a[2]), "r"(a[3]), "r"(b[0]), "r"(b[1]));
}
// interleave position of k within an 8-group so that (kk+lc, kk+lc+4) are adjacent
__device__ __forceinline__ int kpos(int k) {
    return (k & 8) + ((k & 3) << 1) + ((k >> 2) & 1);
}

// --------------------------- rope tables (fp64 like ref) -------------------
__global__ void rope_table_kernel() {
    int idx = blockIdx.x * blockDim.x + threadIdx.x;
    if (idx >= NPOS * 32) return;
    int pos = idx >> 5, j = idx & 31;
    double inv = pow(10000.0, -((double)(2 * j)) / 64.0);
    double ang = (double)pos * inv;
    g_cos[idx] = (float)cos(ang);
    g_sin[idx] = (float)sin(ang);
}

// ------------------------------- init cat ----------------------------------
__global__ void init_kernel(const int* __restrict__ ids,
                            const float* __restrict__ embed,
                            const float* __restrict__ beacon,
                            const float* __restrict__ forget) {
    int idx = blockIdx.x * blockDim.x + threadIdx.x;
    if (idx >= NCAT * DD) return;
    int r = idx >> 10, c = idx & 1023;
    float v;
    if (r < SS)             v = embed[(size_t)ids[r] * DD + c];
    else if (r < SS + MM)   v = beacon[(r - SS) * DD + c];
    else                    v = forget[(r - SS - MM) * DD + c];
    g_cat[idx] = v;
}

// ------------------------------ record/output ------------------------------
__global__ void record_kernel(const float* __restrict__ mem_l,
                              float* __restrict__ out_l) {
    int idx = blockIdx.x * blockDim.x + threadIdx.x;
    if (idx >= MM * DD) return;
    float b = g_cat[SS * DD + idx];
    float f = g_cat[(SS + MM) * DD + idx];
    float g = 1.f / (1.f + expf(-f));
    out_l[idx] = mem_l[idx] * g + b * (1.f - g);
}

// --------------------------------- RMSNorm ---------------------------------
__global__ __launch_bounds__(128) void rms_kernel(const float* __restrict__ in,
                                                  const float* __restrict__ w,
                                                  float* __restrict__ out) {
    const int r = blockIdx.x, tid = threadIdx.x;
    const float4* row4 = (const float4*)(in + (size_t)r * DD);
    float4 v0 = row4[tid], v1 = row4[tid + 128];
    float s = v0.x*v0.x + v0.y*v0.y + v0.z*v0.z + v0.w*v0.w
            + v1.x*v1.x + v1.y*v1.y + v1.z*v1.z + v1.w*v1.w;
#pragma unroll
    for (int o = 16; o > 0; o >>= 1) s += __shfl_down_sync(0xffffffffu, s, o);
    __shared__ float ws[4];
    if ((tid & 31) == 0) ws[tid >> 5] = s;
    __syncthreads();
    float tot = ws[0] + ws[1] + ws[2] + ws[3];
    float inv = rsqrtf(tot * (1.f / DD) + 1e-5f);
    const float4* w4 = (const float4*)w;
    float4* o4 = (float4*)(out + (size_t)r * DD);
    float4 a = w4[tid], b = w4[tid + 128];
    o4[tid]       = make_float4(v0.x*a.x*inv, v0.y*a.y*inv, v0.z*a.z*inv, v0.w*a.w*inv);
    o4[tid + 128] = make_float4(v1.x*b.x*inv, v1.y*b.y*inv, v1.z*b.z*inv, v1.w*b.w*inv);
}

// ----------------------------------- RoPE ----------------------------------
__global__ void rope_kernel(float* __restrict__ buf, int nrows, int mode) {
    int idx = blockIdx.x * blockDim.x + threadIdx.x;
    if (idx >= nrows * HH * 32) return;
    int j = idx & 31, h = (idx >> 5) & 15, r = idx >> 9;
    int pos = (mode == 0) ? ((r < 1152) ? r + 128 : r)
                          : ((r < 1280) ? r : r - 128);
    float c = g_cos[pos * 32 + j];
    float s = g_sin[pos * 32 + j];
    float* p = buf + (size_t)r * DD + h * HDIM + j;
    float x0 = p[0], x1 = p[32];
    p[0]  = x0 * c - x1 * s;
    p[32] = x1 * c + x0 * s;
}

// ------------------- pipelined batched tf32 NN GEMM ------------------------
// C(M,N) = A(M,K) @ B(K,N), row-major, batched over blockIdx.z.
// k-interleaved smem layout: As[m][pos(k)], Bs[n][pos(k)] -> float2 frag LDS.
// vark!=0: per-block-row K = min(K, (blockIdx.y+2)*128)  (attention PV).
struct GPtrs  { const float* A; const float* B; float* C; };
struct GBatch { GPtrs p[16]; };

template <int BM, int BN, int WM, int WN, bool ACC>
__global__ __launch_bounds__(256) void mma_gemm_nn(GBatch batch, int K,
                                                   int lda, int ldb, int ldc,
                                                   int vark) {
    constexpr int BK = 16;
    constexpr int BKP = 24;                 // padded k-stride (banks 8 apart)
    constexpr int WARPS_N = BN / WN;
    constexpr int MT = WM / 16, NT = WN / 8;
    constexpr int AITER = (BM * BK) / (4 * 256);
    constexpr int BITER = (BK * BN) / (4 * 256);
    constexpr int BNQ = BN / 4;
    constexpr int AROWSTEP = 64;
    constexpr int BROWSTEP = 256 / BNQ;

    __shared__ float As[2][BM][BKP];
    __shared__ float Bs[2][BN][BKP];

    const GPtrs pr = batch.p[blockIdx.z];
    const float* __restrict__ A = pr.A;
    const float* __restrict__ B = pr.B;
    float* __restrict__ C = pr.C;
    const int bm = blockIdx.y * BM, bn = blockIdx.x * BN;
    if (vark) K = min(K, ((int)blockIdx.y + 2) * 128);
    const int tid = threadIdx.x, warp = tid >> 5, lane = tid & 31;
    const int wm = (warp / WARPS_N) * WM;
    const int wn = (warp % WARPS_N) * WN;
    const int lr = lane >> 2, lc2 = (lane & 3) * 2;

    const int arow = tid >> 2, ac4 = (tid & 3) * 4;
    const int brow = tid / BNQ, bc4 = (tid % BNQ) * 4;

    float acc[MT][NT][4];
#pragma unroll
    for (int i = 0; i < MT; i++)
#pragma unroll
        for (int j = 0; j < NT; j++)
#pragma unroll
            for (int e = 0; e < 4; e++) acc[i][j][e] = 0.f;

    float4 ar[AITER], br[BITER];

    // prologue: tile 0
#pragma unroll
    for (int it = 0; it < AITER; it++)
        ar[it] = *(const float4*)(A + (size_t)(bm + arow + it * AROWSTEP) * lda + ac4);
#pragma unroll
    for (int it = 0; it < BITER; it++)
        br[it] = *(const float4*)(B + (size_t)(brow + it * BROWSTEP) * ldb + bn + bc4);
#pragma unroll
    for (int it = 0; it < AITER; it++) {
        float* d = As[0][arow + it * AROWSTEP];
        d[kpos(ac4 + 0)] = tf32r(ar[it].x); d[kpos(ac4 + 1)] = tf32r(ar[it].y);
        d[kpos(ac4 + 2)] = tf32r(ar[it].z); d[kpos(ac4 + 3)] = tf32r(ar[it].w);
    }
#pragma unroll
    for (int it = 0; it < BITER; it++) {
        const int kp = kpos(brow + it * BROWSTEP);
        Bs[0][bc4 + 0][kp] = tf32r(br[it].x);
        Bs[0][bc4 + 1][kp] = tf32r(br[it].y);
        Bs[0][bc4 + 2][kp] = tf32r(br[it].z);
        Bs[0][bc4 + 3][kp] = tf32r(br[it].w);
    }
    __syncthreads();

    const int nIter = K / BK;
    for (int itn = 0; itn < nIter; itn++) {
        const int buf = itn & 1;
        const bool more = (itn + 1 < nIter);
        if (more) {
            const int k0 = (itn + 1) * BK;
#pragma unroll
            for (int it = 0; it < AITER; it++)
                ar[it] = *(const float4*)(A + (size_t)(bm + arow + it * AROWSTEP) * lda + k0 + ac4);
#pragma unroll
            for (int it = 0; it < BITER; it++)
                br[it] = *(const float4*)(B + (size_t)(k0 + brow + it * BROWSTEP) * ldb + bn + bc4);
        }
#pragma unroll
        for (int kk = 0; kk < BK; kk += 8) {
            uint32_t af[MT][4], bf[NT][2];
#pragma unroll
            for (int i = 0; i < MT; i++) {
                int r = wm + i * 16 + lr;
                float2 a0 = *(const float2*)&As[buf][r    ][kk + lc2];
                float2 a1 = *(const float2*)&As[buf][r + 8][kk + lc2];
                af[i][0] = __float_as_uint(a0.x);
                af[i][1] = __float_as_uint(a1.x);
                af[i][2] = __float_as_uint(a0.y);
                af[i][3] = __float_as_uint(a1.y);
            }
#pragma unroll
            for (int j = 0; j < NT; j++) {
                int c = wn + j * 8 + lr;
                float2 b0 = *(const float2*)&Bs[buf][c][kk + lc2];
                bf[j][0] = __float_as_uint(b0.x);
                bf[j][1] = __float_as_uint(b0.y);
            }
#pragma unroll
            for (int i = 0; i < MT; i++)
#pragma unroll
                for (int j = 0; j < NT; j++) mma8(acc[i][j], af[i], bf[j]);
        }
        if (more) {
            const int nb = buf ^ 1;
#pragma unroll
            for (int it = 0; it < AITER; it++) {
                float* d = As[nb][arow + it * AROWSTEP];
                d[kpos(ac4 + 0)] = tf32r(ar[it].x); d[kpos(ac4 + 1)] = tf32r(ar[it].y);
                d[kpos(ac4 + 2)] = tf32r(ar[it].z); d[kpos(ac4 + 3)] = tf32r(ar[it].w);
            }
#pragma unroll
            for (int it = 0; it < BITER; it++) {
                const int kp = kpos(brow + it * BROWSTEP);
                Bs[nb][bc4 + 0][kp] = tf32r(br[it].x);
                Bs[nb][bc4 + 1][kp] = tf32r(br[it].y);
                Bs[nb][bc4 + 2][kp] = tf32r(br[it].z);
                Bs[nb][bc4 + 3][kp] = tf32r(br[it].w);
            }
            __syncthreads();
        }
    }

    const int lc = lane & 3;
#pragma unroll
    for (int i = 0; i < MT; i++)
#pragma unroll
        for (int j = 0; j < NT; j++) {
            int r = bm + wm + i * 16 + lr;
            int c = bn + wn + j * 8 + lc * 2;
            float* p0 = C + (size_t)r * ldc + c;
            float* p1 = C + (size_t)(r + 8) * ldc + c;
            if (ACC) {
                p0[0] += acc[i][j][0]; p0[1] += acc[i][j][1];
                p1[0] += acc[i][j][2]; p1[1] += acc[i][j][3];
            } else {
                p0[0] = acc[i][j][0]; p0[1] = acc[i][j][1];
                p1[0] = acc[i][j][2]; p1[1] = acc[i][j][3];
            }
        }
}

// -------------------------- QK^T (NT gemm) + mask --------------------------
__device__ __forceinline__ bool vis_mask(int r, int j) {
    return (r < 1152) ? (j <= r + 128)
                      : (j < 1152 || (j >= 1280 && j - 128 <= r));
}

__global__ __launch_bounds__(256) void qk_kernel(const float* __restrict__ Q,
                                                 const float* __restrict__ Kb,
                                                 float* __restrict__ S) {
    const int bm = blockIdx.y * 128;
    const int bn = blockIdx.x * 128;
    // fully-masked tile skip (hidden + beacon rows)
    if (bm < 1152 && bn >= bm + 256) return;

    constexpr int BK = 32, STR = BK + 4;
    __shared__ float Qs[128][STR];
    __shared__ float Ks[128][STR];

    const int h = blockIdx.z;
    const float* Qh = Q  + h * HDIM;
    const float* Kh = Kb + h * HDIM;
    const int tid = threadIdx.x, warp = tid >> 5, lane = tid & 31;
    const int wm = (warp >> 2) * 64;
    const int wn = (warp & 3) * 32;
    const int lr = lane >> 2, lc = lane & 3;

    float acc[4][4][4];
#pragma unroll
    for (int i = 0; i < 4; i++)
#pragma unroll
        for (int j = 0; j < 4; j++)
#pragma unroll
            for (int e = 0; e < 4; e++) acc[i][j][e] = 0.f;

    for (int k0 = 0; k0 < HDIM; k0 += BK) {
        __syncthreads();
#pragma unroll
        for (int it = 0; it < 4; it++) {
            int f = tid + it * 256;
            int row = f >> 3, c4 = (f & 7) * 4;
            float4 qv = *(const float4*)(Qh + (size_t)(bm + row) * DD + k0 + c4);
            float* dq = &Qs[row][c4];
            dq[0] = tf32r(qv.x); dq[1] = tf32r(qv.y); dq[2] = tf32r(qv.z); dq[3] = tf32r(qv.w);
            float4 kv = *(const float4*)(Kh + (size_t)(bn + row) * DD + k0 + c4);
            float* dk = &Ks[row][c4];
            dk[0] = tf32r(kv.x); dk[1] = tf32r(kv.y); dk[2] = tf32r(kv.z); dk[3] = tf32r(kv.w);
        }
        __syncthreads();
#pragma unroll
        for (int kk = 0; kk < BK; kk += 8) {
            uint32_t af[4][4], bf[4][2];
#pragma unroll
            for (int i = 0; i < 4; i++) {
                int r = wm + i * 16 + lr;
                af[i][0] = __float_as_uint(Qs[r    ][kk + lc    ]);
                af[i][1] = __float_as_uint(Qs[r + 8][kk + lc    ]);
                af[i][2] = __float_as_uint(Qs[r    ][kk + lc + 4]);
                af[i][3] = __float_as_uint(Qs[r + 8][kk + lc + 4]);
            }
#pragma unroll
            for (int j = 0; j < 4; j++) {
                int n = wn + j * 8 + lr;
                bf[j][0] = __float_as_uint(Ks[n][kk + lc    ]);
                bf[j][1] = __float_as_uint(Ks[n][kk + lc + 4]);
            }
#pragma unroll
            for (int i = 0; i < 4; i++)
#pragma unroll
                for (int j = 0; j < 4; j++) mma8(acc[i][j], af[i], bf[j]);
        }
    }

    float* Sh = S + (size_t)h * NCAT * NKR;
#pragma unroll
    for (int i = 0; i < 4; i++)
#pragma unroll
        for (int j = 0; j < 4; j++) {
            int r = bm + wm + i * 16 + lr;
            int c = bn + wn + j * 8 + lc * 2;
            float* p0 = Sh + (size_t)r * NKR + c;
            float* p1 = Sh + (size_t)(r + 8) * NKR + c;
            p0[0] = vis_mask(r,     c    ) ? acc[i][j][0] * 0.125f : -1e30f;
            p0[1] = vis_mask(r,     c + 1) ? acc[i][j][1] * 0.125f : -1e30f;
            p1[0] = vis_mask(r + 8, c    ) ? acc[i][j][2] * 0.125f : -1e30f;
            p1[1] = vis_mask(r + 8, c + 1) ? acc[i][j][3] * 0.125f : -1e30f;
        }
}

// ------------------------- softmax (2-pass, bounded) -----------------------
__global__ __launch_bounds__(128) void softmax_kernel(float* __restrict__ S) {
    const int r = blockIdx.x;
    const int limit = (r < 1152) ? min(((r >> 7) + 2) << 7, NKR) : NKR;
    float* row = S + ((size_t)blockIdx.y * NCAT + r) * NKR;
    __shared__ float sm[128], ss[128];
    const int tid = threadIdx.x;

    float m = -3.402823466e38f, s = 0.f;
    for (int j = tid; j < limit; j += 128) {
        float x = row[j];
        float mn = fmaxf(m, x);
        s = s * __expf(m - mn) + __expf(x - mn);
        m = mn;
    }
    sm[tid] = m; ss[tid] = s; __syncthreads();
    for (int t = 64; t > 0; t >>= 1) {
        if (tid < t) {
            float m2 = sm[tid + t], s2 = ss[tid + t];
            float mn = fmaxf(m, m2);
            s = s * __expf(m - mn) + s2 * __expf(m2 - mn);
            m = mn;
            sm[tid] = m; ss[tid] = s;
        }
        __syncthreads();
    }
    const float mx = sm[0];
    const float inv = 1.f / ss[0];
    for (int j = tid; j < limit; j += 128)
        row[j] = __expf(row[j] - mx) * inv;
}

// ------------------------------ silu(g) * u --------------------------------
__global__ void silu_mul_kernel(float* __restrict__ gbuf,
                                const float* __restrict__ ubuf) {
    int idx = blockIdx.x * blockDim.x + threadIdx.x;
    if (idx >= NCAT * FF) return;
    float g = gbuf[idx];
    gbuf[idx] = g / (1.f + expf(-g)) * ubuf[idx];
}

// --------------------------------- host ------------------------------------
extern "C" void kernel_launch(void* const* d_in, const int* in_sizes, int n_in,
                              void* d_out, int out_size) {
    (void)in_sizes; (void)n_in; (void)out_size;
    const int*   ids    = (const int*)  d_in[0];
    const float* memory = (const float*)d_in[1];
    const float* beacon = (const float*)d_in[2];
    const float* forget = (const float*)d_in[3];
    const float* embed  = (const float*)d_in[4];
    const float* ln1    = (const float*)d_in[5];
    const float* ln2    = (const float*)d_in[6];
    const float* Wq     = (const float*)d_in[7];
    const float* Wk     = (const float*)d_in[8];
    const float* Wv     = (const float*)d_in[9];
    const float* Wo     = (const float*)d_in[10];
    const float* mWk    = (const float*)d_in[11];
    const float* mWv    = (const float*)d_in[12];
    const float* bWq    = (const float*)d_in[13];
    const float* bWk    = (const float*)d_in[14];
    const float* bWv    = (const float*)d_in[15];
    const float* fWq    = (const float*)d_in[16];
    const float* fWk    = (const float*)d_in[17];
    const float* fWv    = (const float*)d_in[18];
    const float* Wg     = (const float*)d_in[19];
    const float* Wu     = (const float*)d_in[20];
    const float* Wd     = (const float*)d_in[21];
    float* out = (float*)d_out;

    float *cat, *x, *q, *k, *v, *attn, *ffg, *ffu, *scores;
    cudaGetSymbolAddress((void**)&cat,    g_cat);
    cudaGetSymbolAddress((void**)&x,      g_x);
    cudaGetSymbolAddress((void**)&q,      g_q);
    cudaGetSymbolAddress((void**)&k,      g_k);
    cudaGetSymbolAddress((void**)&v,      g_v);
    cudaGetSymbolAddress((void**)&attn,   g_attn);
    cudaGetSymbolAddress((void**)&ffg,    g_ffg);
    cudaGetSymbolAddress((void**)&ffu,    g_ffu);
    cudaGetSymbolAddress((void**)&scores, g_scores);

    rope_table_kernel<<<(NPOS * 32 + 255) / 256, 256>>>();
    init_kernel<<<(NCAT * DD + 255) / 256, 256>>>(ids, embed, beacon, forget);

    const size_t WSZ = (size_t)DD * DD;
    const size_t FSZ = (size_t)DD * FF;

    for (int l = 0; l < LL; l++) {
        const float* mem_l = memory + (size_t)l * MM * DD;
        record_kernel<<<(MM * DD + 255) / 256, 256>>>(mem_l, out + (size_t)l * MM * DD);
        if (l == LL - 1) break;   // layer 7's compute is never consumed

        const float* wq  = Wq  + (size_t)l * WSZ;
        const float* wk  = Wk  + (size_t)l * WSZ;
        const float* wv  = Wv  + (size_t)l * WSZ;
        const float* wo  = Wo  + (size_t)l * WSZ;
        const float* mwk = mWk + (size_t)l * WSZ;
        const float* mwv = mWv + (size_t)l * WSZ;
        const float* bwq = bWq + (size_t)l * WSZ;
        const float* bwk = bWk + (size_t)l * WSZ;
        const float* bwv = bWv + (size_t)l * WSZ;
        const float* fwq = fWq + (size_t)l * WSZ;
        const float* fwk = fWk + (size_t)l * WSZ;
        const float* fwv = fWv + (size_t)l * WSZ;
        const float* wg  = Wg  + (size_t)l * FSZ;
        const float* wu  = Wu  + (size_t)l * FSZ;
        const float* wd  = Wd  + (size_t)l * FSZ;

        rms_kernel<<<NCAT, 128>>>(cat, ln1 + (size_t)l * DD, x);

        // big projections on hidden rows (M=1024, z=3)
        {
            GBatch bb{};
            bb.p[0] = { x, wq, q };
            bb.p[1] = { x, wk, k + (size_t)MM * DD };
            bb.p[2] = { x, wv, v + (size_t)MM * DD };
            mma_gemm_nn<128,128,64,32,false><<<dim3(8,8,3), 256>>>(bb, DD, DD, DD, DD, 0);
        }
        // small projections (M=128, z=8), BN=64 for fill
        {
            GBatch sb{};
            sb.p[0] = { mem_l,                  mwk, k };
            sb.p[1] = { mem_l,                  mwv, v };
            sb.p[2] = { x + (size_t)SS*DD,      bwq, q + (size_t)SS*DD };
            sb.p[3] = { x + (size_t)SS*DD,      bwk, k + (size_t)(MM+SS)*DD };
            sb.p[4] = { x + (size_t)SS*DD,      bwv, v + (size_t)(MM+SS)*DD };
            sb.p[5] = { x + (size_t)(SS+MM)*DD, fwq, q + (size_t)(SS+MM)*DD };
            sb.p[6] = { x + (size_t)(SS+MM)*DD, fwk, k + (size_t)(MM+SS+MM)*DD };
            sb.p[7] = { x + (size_t)(SS+MM)*DD, fwv, v + (size_t)(MM+SS+MM)*DD };
            mma_gemm_nn<128,64,32,32,false><<<dim3(16,1,8), 256>>>(sb, DD, DD, DD, DD, 0);
        }

        rope_kernel<<<(NCAT * HH * 32 + 255) / 256, 256>>>(q, NCAT, 0);
        rope_kernel<<<(NKR  * HH * 32 + 255) / 256, 256>>>(k, NKR,  1);

        // attention
        qk_kernel<<<dim3(11, 10, 16), 256>>>(q, k, scores);
        softmax_kernel<<<dim3(NCAT, HH), 128>>>(scores);
        {
            GBatch av{};
            for (int h = 0; h < HH; h++)
                av.p[h] = { scores + (size_t)h * NCAT * NKR, v + h * HDIM, attn + h * HDIM };
            mma_gemm_nn<128,64,32,32,false><<<dim3(1,10,16), 256>>>(av, NKR, NKR, DD, DD, 1);
        }
        // cat += attn @ Wo  (BN=64 -> 160 blocks)
        {
            GBatch ob{};
            ob.p[0] = { attn, wo, cat };
            mma_gemm_nn<128,64,32,32,true><<<dim3(16,10,1), 256>>>(ob, DD, DD, DD, DD, 0);
        }

        // MLP
        rms_kernel<<<NCAT, 128>>>(cat, ln2 + (size_t)l * DD, x);
        {
            GBatch mb{};
            mb.p[0] = { x, wg, ffg };
            mb.p[1] = { x, wu, ffu };
            mma_gemm_nn<128,128,64,32,false><<<dim3(16,10,2), 256>>>(mb, DD, DD, FF, FF, 0);
        }
        silu_mul_kernel<<<(NCAT * FF + 255) / 256, 256>>>(ffg, ffu);
        // cat += ffg @ Wd  (BN=64 -> 160 blocks)
        {
            GBatch db{};
            db.p[0] = { ffg, wd, cat };
            mma_gemm_nn<128,64,32,32,true><<<dim3(16,10,1), 256>>>(db, FF, FF, DD, DD, 0);
        }
    }
}

// round 7
// speedup vs baseline: 1.6527x; 1.6527x over previous
#include <cuda_runtime.h>
#include <math.h>
#include <stdint.h>

// ---------------------------------------------------------------------------
// Encoder_51582557225690 : 8-layer beacon/forget memory transformer.
// R7: R5's proven GEMM (float4 STS fill / LDS.32 frags, double-buffered)
// + attention masked-tile skipping (qk skip, bounded softmax, vark PV).
// L=8 D=1024 H=16 HD=64 S=1024 M=128 F=2048 B=1
// ---------------------------------------------------------------------------

#define DD    1024
#define HH    16
#define HDIM  64
#define SS    1024
#define MM    128
#define LL    8
#define FF    2048
#define NCAT  1280
#define NKR   1408
#define NPOS  1280

// ------------------------- device scratch (no allocs) ----------------------
__device__ float g_cat [NCAT * DD];
__device__ float g_x   [NCAT * DD];
__device__ float g_q   [NCAT * DD];
__device__ float g_k   [NKR  * DD];
__device__ float g_v   [NKR  * DD];
__device__ float g_attn[NCAT * DD];
__device__ float g_ffg [NCAT * FF];
__device__ float g_ffu [NCAT * FF];
__device__ float g_scores[(size_t)HH * NCAT * NKR];   // 115 MB BSS scratch
__device__ float g_cos [NPOS * 32];
__device__ float g_sin [NPOS * 32];

// ------------------------------- tf32 helpers ------------------------------
__device__ __forceinline__ float tf32r(float x) {
    uint32_t u;
    asm("cvt.rna.tf32.f32 %0, %1;" : "=r"(u) : "f"(x));
    return __uint_as_float(u);
}
__device__ __forceinline__ void mma8(float* c, const uint32_t* a, const uint32_t* b) {
    asm volatile(
        "mma.sync.aligned.m16n8k8.row.col.f32.tf32.tf32.f32 "
        "{%0,%1,%2,%3},{%4,%5,%6,%7},{%8,%9},{%0,%1,%2,%3};"
        : "+f"(c[0]), "+f"(c[1]), "+f"(c[2]), "+f"(c[3])
        : "r"(a[0]), "r"(a[1]), "r"(a[2]), "r"(a[3]), "r"(b[0]), "r"(b[1]));
}

// --------------------------- rope tables (fp64 like ref) -------------------
__global__ void rope_table_kernel() {
    int idx = blockIdx.x * blockDim.x + threadIdx.x;
    if (idx >= NPOS * 32) return;
    int pos = idx >> 5, j = idx & 31;
    double inv = pow(10000.0, -((double)(2 * j)) / 64.0);
    double ang = (double)pos * inv;
    g_cos[idx] = (float)cos(ang);
    g_sin[idx] = (float)sin(ang);
}

// ------------------------------- init cat ----------------------------------
__global__ void init_kernel(const int* __restrict__ ids,
                            const float* __restrict__ embed,
                            const float* __restrict__ beacon,
                            const float* __restrict__ forget) {
    int idx = blockIdx.x * blockDim.x + threadIdx.x;
    if (idx >= NCAT * DD) return;
    int r = idx >> 10, c = idx & 1023;
    float v;
    if (r < SS)             v = embed[(size_t)ids[r] * DD + c];
    else if (r < SS + MM)   v = beacon[(r - SS) * DD + c];
    else                    v = forget[(r - SS - MM) * DD + c];
    g_cat[idx] = v;
}

// ------------------------------ record/output ------------------------------
__global__ void record_kernel(const float* __restrict__ mem_l,
                              float* __restrict__ out_l) {
    int idx = blockIdx.x * blockDim.x + threadIdx.x;
    if (idx >= MM * DD) return;
    float b = g_cat[SS * DD + idx];
    float f = g_cat[(SS + MM) * DD + idx];
    float g = 1.f / (1.f + expf(-f));
    out_l[idx] = mem_l[idx] * g + b * (1.f - g);
}

// --------------------------------- RMSNorm ---------------------------------
__global__ __launch_bounds__(128) void rms_kernel(const float* __restrict__ in,
                                                  const float* __restrict__ w,
                                                  float* __restrict__ out) {
    const int r = blockIdx.x, tid = threadIdx.x;
    const float4* row4 = (const float4*)(in + (size_t)r * DD);
    float4 v0 = row4[tid], v1 = row4[tid + 128];
    float s = v0.x*v0.x + v0.y*v0.y + v0.z*v0.z + v0.w*v0.w
            + v1.x*v1.x + v1.y*v1.y + v1.z*v1.z + v1.w*v1.w;
#pragma unroll
    for (int o = 16; o > 0; o >>= 1) s += __shfl_down_sync(0xffffffffu, s, o);
    __shared__ float ws[4];
    if ((tid & 31) == 0) ws[tid >> 5] = s;
    __syncthreads();
    float tot = ws[0] + ws[1] + ws[2] + ws[3];
    float inv = rsqrtf(tot * (1.f / DD) + 1e-5f);
    const float4* w4 = (const float4*)w;
    float4* o4 = (float4*)(out + (size_t)r * DD);
    float4 a = w4[tid], b = w4[tid + 128];
    o4[tid]       = make_float4(v0.x*a.x*inv, v0.y*a.y*inv, v0.z*a.z*inv, v0.w*a.w*inv);
    o4[tid + 128] = make_float4(v1.x*b.x*inv, v1.y*b.y*inv, v1.z*b.z*inv, v1.w*b.w*inv);
}

// ----------------------------------- RoPE ----------------------------------
__global__ void rope_kernel(float* __restrict__ buf, int nrows, int mode) {
    int idx = blockIdx.x * blockDim.x + threadIdx.x;
    if (idx >= nrows * HH * 32) return;
    int j = idx & 31, h = (idx >> 5) & 15, r = idx >> 9;
    int pos = (mode == 0) ? ((r < 1152) ? r + 128 : r)
                          : ((r < 1280) ? r : r - 128);
    float c = g_cos[pos * 32 + j];
    float s = g_sin[pos * 32 + j];
    float* p = buf + (size_t)r * DD + h * HDIM + j;
    float x0 = p[0], x1 = p[32];
    p[0]  = x0 * c - x1 * s;
    p[32] = x1 * c + x0 * s;
}

// ------------------- pipelined batched tf32 NN GEMM ------------------------
// C(M,N) = A(M,K) @ B(K,N), row-major, batched over blockIdx.z.
// Double-buffered smem + register prefetch; one __syncthreads per BK=16.
// vark!=0: per-block-row K = min(K, (blockIdx.y+2)*128)  (attention PV).
struct GPtrs  { const float* A; const float* B; float* C; };
struct GBatch { GPtrs p[16]; };

template <int BM, int BN, int WM, int WN, bool ACC>
__global__ __launch_bounds__(256) void mma_gemm_nn(GBatch batch, int K,
                                                   int lda, int ldb, int ldc,
                                                   int vark) {
    constexpr int BK = 16;
    constexpr int WARPS_N = BN / WN;
    constexpr int MT = WM / 16, NT = WN / 8;
    constexpr int ASTR = BK + 4;
    constexpr int BSTR = BN + 8;
    constexpr int AITER = (BM * BK) / (4 * 256);
    constexpr int BITER = (BK * BN) / (4 * 256);
    constexpr int BNQ = BN / 4;
    constexpr int AROWSTEP = 64;
    constexpr int BROWSTEP = 256 / BNQ;

    __shared__ float As[2][BM][ASTR];
    __shared__ float Bs[2][BK][BSTR];

    const GPtrs pr = batch.p[blockIdx.z];
    const float* __restrict__ A = pr.A;
    const float* __restrict__ B = pr.B;
    float* __restrict__ C = pr.C;
    const int bm = blockIdx.y * BM, bn = blockIdx.x * BN;
    if (vark) K = min(K, ((int)blockIdx.y + 2) * 128);
    const int tid = threadIdx.x, warp = tid >> 5, lane = tid & 31;
    const int wm = (warp / WARPS_N) * WM;
    const int wn = (warp % WARPS_N) * WN;
    const int lr = lane >> 2, lc = lane & 3;

    const int arow = tid >> 2, ac4 = (tid & 3) * 4;
    const int brow = tid / BNQ, bc4 = (tid % BNQ) * 4;

    float acc[MT][NT][4];
#pragma unroll
    for (int i = 0; i < MT; i++)
#pragma unroll
        for (int j = 0; j < NT; j++)
#pragma unroll
            for (int e = 0; e < 4; e++) acc[i][j][e] = 0.f;

    float4 ar[AITER], br[BITER];

    // prologue: tile 0
#pragma unroll
    for (int it = 0; it < AITER; it++)
        ar[it] = *(const float4*)(A + (size_t)(bm + arow + it * AROWSTEP) * lda + ac4);
#pragma unroll
    for (int it = 0; it < BITER; it++)
        br[it] = *(const float4*)(B + (size_t)(brow + it * BROWSTEP) * ldb + bn + bc4);
#pragma unroll
    for (int it = 0; it < AITER; it++) {
        float* d = &As[0][arow + it * AROWSTEP][ac4];
        d[0] = tf32r(ar[it].x); d[1] = tf32r(ar[it].y);
        d[2] = tf32r(ar[it].z); d[3] = tf32r(ar[it].w);
    }
#pragma unroll
    for (int it = 0; it < BITER; it++) {
        float* d = &Bs[0][brow + it * BROWSTEP][bc4];
        d[0] = tf32r(br[it].x); d[1] = tf32r(br[it].y);
        d[2] = tf32r(br[it].z); d[3] = tf32r(br[it].w);
    }
    __syncthreads();

    const int nIter = K / BK;
    for (int itn = 0; itn < nIter; itn++) {
        const int buf = itn & 1;
        const bool more = (itn + 1 < nIter);
        if (more) {
            const int k0 = (itn + 1) * BK;
#pragma unroll
            for (int it = 0; it < AITER; it++)
                ar[it] = *(const float4*)(A + (size_t)(bm + arow + it * AROWSTEP) * lda + k0 + ac4);
#pragma unroll
            for (int it = 0; it < BITER; it++)
                br[it] = *(const float4*)(B + (size_t)(k0 + brow + it * BROWSTEP) * ldb + bn + bc4);
        }
#pragma unroll
        for (int kk = 0; kk < BK; kk += 8) {
            uint32_t af[MT][4], bf[NT][2];
#pragma unroll
            for (int i = 0; i < MT; i++) {
                int r = wm + i * 16 + lr;
                af[i][0] = __float_as_uint(As[buf][r    ][kk + lc    ]);
                af[i][1] = __float_as_uint(As[buf][r + 8][kk + lc    ]);
                af[i][2] = __float_as_uint(As[buf][r    ][kk + lc + 4]);
                af[i][3] = __float_as_uint(As[buf][r + 8][kk + lc + 4]);
            }
#pragma unroll
            for (int j = 0; j < NT; j++) {
                int c = wn + j * 8 + lr;
                bf[j][0] = __float_as_uint(Bs[buf][kk + lc    ][c]);
                bf[j][1] = __float_as_uint(Bs[buf][kk + lc + 4][c]);
            }
#pragma unroll
            for (int i = 0; i < MT; i++)
#pragma unroll
                for (int j = 0; j < NT; j++) mma8(acc[i][j], af[i], bf[j]);
        }
        if (more) {
            const int nb = buf ^ 1;
#pragma unroll
            for (int it = 0; it < AITER; it++) {
                float* d = &As[nb][arow + it * AROWSTEP][ac4];
                d[0] = tf32r(ar[it].x); d[1] = tf32r(ar[it].y);
                d[2] = tf32r(ar[it].z); d[3] = tf32r(ar[it].w);
            }
#pragma unroll
            for (int it = 0; it < BITER; it++) {
                float* d = &Bs[nb][brow + it * BROWSTEP][bc4];
                d[0] = tf32r(br[it].x); d[1] = tf32r(br[it].y);
                d[2] = tf32r(br[it].z); d[3] = tf32r(br[it].w);
            }
            __syncthreads();
        }
    }

#pragma unroll
    for (int i = 0; i < MT; i++)
#pragma unroll
        for (int j = 0; j < NT; j++) {
            int r = bm + wm + i * 16 + lr;
            int c = bn + wn + j * 8 + lc * 2;
            float* p0 = C + (size_t)r * ldc + c;
            float* p1 = C + (size_t)(r + 8) * ldc + c;
            if (ACC) {
                p0[0] += acc[i][j][0]; p0[1] += acc[i][j][1];
                p1[0] += acc[i][j][2]; p1[1] += acc[i][j][3];
            } else {
                p0[0] = acc[i][j][0]; p0[1] = acc[i][j][1];
                p1[0] = acc[i][j][2]; p1[1] = acc[i][j][3];
            }
        }
}

// -------------------------- QK^T (NT gemm) + mask --------------------------
__device__ __forceinline__ bool vis_mask(int r, int j) {
    return (r < 1152) ? (j <= r + 128)
                      : (j < 1152 || (j >= 1280 && j - 128 <= r));
}

__global__ __launch_bounds__(256) void qk_kernel(const float* __restrict__ Q,
                                                 const float* __restrict__ Kb,
                                                 float* __restrict__ S) {
    const int bm = blockIdx.y * 128;
    const int bn = blockIdx.x * 128;
    // fully-masked tile skip (hidden + beacon rows): keys start at bm+256
    if (bm < 1152 && bn >= bm + 256) return;

    constexpr int BK = 32, STR = BK + 4;
    __shared__ float Qs[128][STR];
    __shared__ float Ks[128][STR];

    const int h = blockIdx.z;
    const float* Qh = Q  + h * HDIM;
    const float* Kh = Kb + h * HDIM;
    const int tid = threadIdx.x, warp = tid >> 5, lane = tid & 31;
    const int wm = (warp >> 2) * 64;
    const int wn = (warp & 3) * 32;
    const int lr = lane >> 2, lc = lane & 3;

    float acc[4][4][4];
#pragma unroll
    for (int i = 0; i < 4; i++)
#pragma unroll
        for (int j = 0; j < 4; j++)
#pragma unroll
            for (int e = 0; e < 4; e++) acc[i][j][e] = 0.f;

    for (int k0 = 0; k0 < HDIM; k0 += BK) {
        __syncthreads();
#pragma unroll
        for (int it = 0; it < 4; it++) {
            int f = tid + it * 256;
            int row = f >> 3, c4 = (f & 7) * 4;
            float4 qv = *(const float4*)(Qh + (size_t)(bm + row) * DD + k0 + c4);
            float* dq = &Qs[row][c4];
            dq[0] = tf32r(qv.x); dq[1] = tf32r(qv.y); dq[2] = tf32r(qv.z); dq[3] = tf32r(qv.w);
            float4 kv = *(const float4*)(Kh + (size_t)(bn + row) * DD + k0 + c4);
            float* dk = &Ks[row][c4];
            dk[0] = tf32r(kv.x); dk[1] = tf32r(kv.y); dk[2] = tf32r(kv.z); dk[3] = tf32r(kv.w);
        }
        __syncthreads();
#pragma unroll
        for (int kk = 0; kk < BK; kk += 8) {
            uint32_t af[4][4], bf[4][2];
#pragma unroll
            for (int i = 0; i < 4; i++) {
                int r = wm + i * 16 + lr;
                af[i][0] = __float_as_uint(Qs[r    ][kk + lc    ]);
                af[i][1] = __float_as_uint(Qs[r + 8][kk + lc    ]);
                af[i][2] = __float_as_uint(Qs[r    ][kk + lc + 4]);
                af[i][3] = __float_as_uint(Qs[r + 8][kk + lc + 4]);
            }
#pragma unroll
            for (int j = 0; j < 4; j++) {
                int n = wn + j * 8 + lr;
                bf[j][0] = __float_as_uint(Ks[n][kk + lc    ]);
                bf[j][1] = __float_as_uint(Ks[n][kk + lc + 4]);
            }
#pragma unroll
            for (int i = 0; i < 4; i++)
#pragma unroll
                for (int j = 0; j < 4; j++) mma8(acc[i][j], af[i], bf[j]);
        }
    }

    float* Sh = S + (size_t)h * NCAT * NKR;
#pragma unroll
    for (int i = 0; i < 4; i++)
#pragma unroll
        for (int j = 0; j < 4; j++) {
            int r = bm + wm + i * 16 + lr;
            int c = bn + wn + j * 8 + lc * 2;
            float* p0 = Sh + (size_t)r * NKR + c;
            float* p1 = Sh + (size_t)(r + 8) * NKR + c;
            p0[0] = vis_mask(r,     c    ) ? acc[i][j][0] * 0.125f : -1e30f;
            p0[1] = vis_mask(r,     c + 1) ? acc[i][j][1] * 0.125f : -1e30f;
            p1[0] = vis_mask(r + 8, c    ) ? acc[i][j][2] * 0.125f : -1e30f;
            p1[1] = vis_mask(r + 8, c + 1) ? acc[i][j][3] * 0.125f : -1e30f;
        }
}

// ------------------------- softmax (2-pass, bounded) -----------------------
__global__ __launch_bounds__(128) void softmax_kernel(float* __restrict__ S) {
    const int r = blockIdx.x;
    const int limit = (r < 1152) ? min(((r >> 7) + 2) << 7, NKR) : NKR;
    float* row = S + ((size_t)blockIdx.y * NCAT + r) * NKR;
    __shared__ float sm[128], ss[128];
    const int tid = threadIdx.x;

    float m = -3.402823466e38f, s = 0.f;
    for (int j = tid; j < limit; j += 128) {
        float x = row[j];
        float mn = fmaxf(m, x);
        s = s * __expf(m - mn) + __expf(x - mn);
        m = mn;
    }
    sm[tid] = m; ss[tid] = s; __syncthreads();
    for (int t = 64; t > 0; t >>= 1) {
        if (tid < t) {
            float m2 = sm[tid + t], s2 = ss[tid + t];
            float mn = fmaxf(m, m2);
            s = s * __expf(m - mn) + s2 * __expf(m2 - mn);
            m = mn;
            sm[tid] = m; ss[tid] = s;
        }
        __syncthreads();
    }
    const float mx = sm[0];
    const float inv = 1.f / ss[0];
    for (int j = tid; j < limit; j += 128)
        row[j] = __expf(row[j] - mx) * inv;
}

// ------------------------------ silu(g) * u --------------------------------
__global__ void silu_mul_kernel(float* __restrict__ gbuf,
                                const float* __restrict__ ubuf) {
    int idx = blockIdx.x * blockDim.x + threadIdx.x;
    if (idx >= NCAT * FF) return;
    float g = gbuf[idx];
    gbuf[idx] = g / (1.f + expf(-g)) * ubuf[idx];
}

// --------------------------------- host ------------------------------------
extern "C" void kernel_launch(void* const* d_in, const int* in_sizes, int n_in,
                              void* d_out, int out_size) {
    (void)in_sizes; (void)n_in; (void)out_size;
    const int*   ids    = (const int*)  d_in[0];
    const float* memory = (const float*)d_in[1];
    const float* beacon = (const float*)d_in[2];
    const float* forget = (const float*)d_in[3];
    const float* embed  = (const float*)d_in[4];
    const float* ln1    = (const float*)d_in[5];
    const float* ln2    = (const float*)d_in[6];
    const float* Wq     = (const float*)d_in[7];
    const float* Wk     = (const float*)d_in[8];
    const float* Wv     = (const float*)d_in[9];
    const float* Wo     = (const float*)d_in[10];
    const float* mWk    = (const float*)d_in[11];
    const float* mWv    = (const float*)d_in[12];
    const float* bWq    = (const float*)d_in[13];
    const float* bWk    = (const float*)d_in[14];
    const float* bWv    = (const float*)d_in[15];
    const float* fWq    = (const float*)d_in[16];
    const float* fWk    = (const float*)d_in[17];
    const float* fWv    = (const float*)d_in[18];
    const float* Wg     = (const float*)d_in[19];
    const float* Wu     = (const float*)d_in[20];
    const float* Wd     = (const float*)d_in[21];
    float* out = (float*)d_out;

    float *cat, *x, *q, *k, *v, *attn, *ffg, *ffu, *scores;
    cudaGetSymbolAddress((void**)&cat,    g_cat);
    cudaGetSymbolAddress((void**)&x,      g_x);
    cudaGetSymbolAddress((void**)&q,      g_q);
    cudaGetSymbolAddress((void**)&k,      g_k);
    cudaGetSymbolAddress((void**)&v,      g_v);
    cudaGetSymbolAddress((void**)&attn,   g_attn);
    cudaGetSymbolAddress((void**)&ffg,    g_ffg);
    cudaGetSymbolAddress((void**)&ffu,    g_ffu);
    cudaGetSymbolAddress((void**)&scores, g_scores);

    rope_table_kernel<<<(NPOS * 32 + 255) / 256, 256>>>();
    init_kernel<<<(NCAT * DD + 255) / 256, 256>>>(ids, embed, beacon, forget);

    const size_t WSZ = (size_t)DD * DD;
    const size_t FSZ = (size_t)DD * FF;

    for (int l = 0; l < LL; l++) {
        const float* mem_l = memory + (size_t)l * MM * DD;
        record_kernel<<<(MM * DD + 255) / 256, 256>>>(mem_l, out + (size_t)l * MM * DD);
        if (l == LL - 1) break;   // layer 7's compute is never consumed

        const float* wq  = Wq  + (size_t)l * WSZ;
        const float* wk  = Wk  + (size_t)l * WSZ;
        const float* wv  = Wv  + (size_t)l * WSZ;
        const float* wo  = Wo  + (size_t)l * WSZ;
        const float* mwk = mWk + (size_t)l * WSZ;
        const float* mwv = mWv + (size_t)l * WSZ;
        const float* bwq = bWq + (size_t)l * WSZ;
        const float* bwk = bWk + (size_t)l * WSZ;
        const float* bwv = bWv + (size_t)l * WSZ;
        const float* fwq = fWq + (size_t)l * WSZ;
        const float* fwk = fWk + (size_t)l * WSZ;
        const float* fwv = fWv + (size_t)l * WSZ;
        const float* wg  = Wg  + (size_t)l * FSZ;
        const float* wu  = Wu  + (size_t)l * FSZ;
        const float* wd  = Wd  + (size_t)l * FSZ;

        rms_kernel<<<NCAT, 128>>>(cat, ln1 + (size_t)l * DD, x);

        // big projections on hidden rows (M=1024, z=3)
        {
            GBatch bb{};
            bb.p[0] = { x, wq, q };
            bb.p[1] = { x, wk, k + (size_t)MM * DD };
            bb.p[2] = { x, wv, v + (size_t)MM * DD };
            mma_gemm_nn<128,128,64,32,false><<<dim3(8,8,3), 256>>>(bb, DD, DD, DD, DD, 0);
        }
        // small projections (M=128, z=8), BN=64 for fill
        {
            GBatch sb{};
            sb.p[0] = { mem_l,                  mwk, k };
            sb.p[1] = { mem_l,                  mwv, v };
            sb.p[2] = { x + (size_t)SS*DD,      bwq, q + (size_t)SS*DD };
            sb.p[3] = { x + (size_t)SS*DD,      bwk, k + (size_t)(MM+SS)*DD };
            sb.p[4] = { x + (size_t)SS*DD,      bwv, v + (size_t)(MM+SS)*DD };
            sb.p[5] = { x + (size_t)(SS+MM)*DD, fwq, q + (size_t)(SS+MM)*DD };
            sb.p[6] = { x + (size_t)(SS+MM)*DD, fwk, k + (size_t)(MM+SS+MM)*DD };
            sb.p[7] = { x + (size_t)(SS+MM)*DD, fwv, v + (size_t)(MM+SS+MM)*DD };
            mma_gemm_nn<128,64,32,32,false><<<dim3(16,1,8), 256>>>(sb, DD, DD, DD, DD, 0);
        }

        rope_kernel<<<(NCAT * HH * 32 + 255) / 256, 256>>>(q, NCAT, 0);
        rope_kernel<<<(NKR  * HH * 32 + 255) / 256, 256>>>(k, NKR,  1);

        // attention
        qk_kernel<<<dim3(11, 10, 16), 256>>>(q, k, scores);
        softmax_kernel<<<dim3(NCAT, HH), 128>>>(scores);
        {
            GBatch av{};
            for (int h = 0; h < HH; h++)
                av.p[h] = { scores + (size_t)h * NCAT * NKR, v + h * HDIM, attn + h * HDIM };
            mma_gemm_nn<128,64,32,32,false><<<dim3(1,10,16), 256>>>(av, NKR, NKR, DD, DD, 1);
        }
        // cat += attn @ Wo  (BN=64 -> 160 blocks)
        {
            GBatch ob{};
            ob.p[0] = { attn, wo, cat };
            mma_gemm_nn<128,64,32,32,true><<<dim3(16,10,1), 256>>>(ob, DD, DD, DD, DD, 0);
        }

        // MLP
        rms_kernel<<<NCAT, 128>>>(cat, ln2 + (size_t)l * DD, x);
        {
            GBatch mb{};
            mb.p[0] = { x, wg, ffg };
            mb.p[1] = { x, wu, ffu };
            mma_gemm_nn<128,128,64,32,false><<<dim3(16,10,2), 256>>>(mb, DD, DD, FF, FF, 0);
        }
        silu_mul_kernel<<<(NCAT * FF + 255) / 256, 256>>>(ffg, ffu);
        // cat += ffg @ Wd  (BN=64 -> 160 blocks)
        {
            GBatch db{};
            db.p[0] = { ffg, wd, cat };
            mma_gemm_nn<128,64,32,32,true><<<dim3(16,10,1), 256>>>(db, FF, FF, DD, DD, 0);
        }
    }
}

// round 9
// speedup vs baseline: 1.8818x; 1.1386x over previous
#include <cuda_runtime.h>
#include <math.h>
#include <stdint.h>

// ---------------------------------------------------------------------------
// Encoder_51582557225690 : 8-layer beacon/forget memory transformer.
// R8: fused flash attention (Q-in-regs, online softmax, P through smem),
// on top of R7's proven pipelined tf32 GEMM + masked-tile analysis.
// L=8 D=1024 H=16 HD=64 S=1024 M=128 F=2048 B=1
// ---------------------------------------------------------------------------

#define DD    1024
#define HH    16
#define HDIM  64
#define SS    1024
#define MM    128
#define LL    8
#define FF    2048
#define NCAT  1280
#define NKR   1408
#define NPOS  1280

// ------------------------- device scratch (no allocs) ----------------------
__device__ float g_cat [NCAT * DD];
__device__ float g_x   [NCAT * DD];
__device__ float g_q   [NCAT * DD];
__device__ float g_k   [NKR  * DD];
__device__ float g_v   [NKR  * DD];
__device__ float g_attn[NCAT * DD];
__device__ float g_ffg [NCAT * FF];
__device__ float g_ffu [NCAT * FF];
__device__ float g_cos [NPOS * 32];
__device__ float g_sin [NPOS * 32];

// ------------------------------- tf32 helpers ------------------------------
__device__ __forceinline__ float tf32r(float x) {
    uint32_t u;
    asm("cvt.rna.tf32.f32 %0, %1;" : "=r"(u) : "f"(x));
    return __uint_as_float(u);
}
__device__ __forceinline__ void mma8(float* c, const uint32_t* a, const uint32_t* b) {
    asm volatile(
        "mma.sync.aligned.m16n8k8.row.col.f32.tf32.tf32.f32 "
        "{%0,%1,%2,%3},{%4,%5,%6,%7},{%8,%9},{%0,%1,%2,%3};"
        : "+f"(c[0]), "+f"(c[1]), "+f"(c[2]), "+f"(c[3])
        : "r"(a[0]), "r"(a[1]), "r"(a[2]), "r"(a[3]), "r"(b[0]), "r"(b[1]));
}

// --------------------------- rope tables (fp64 like ref) -------------------
__global__ void rope_table_kernel() {
    int idx = blockIdx.x * blockDim.x + threadIdx.x;
    if (idx >= NPOS * 32) return;
    int pos = idx >> 5, j = idx & 31;
    double inv = pow(10000.0, -((double)(2 * j)) / 64.0);
    double ang = (double)pos * inv;
    g_cos[idx] = (float)cos(ang);
    g_sin[idx] = (float)sin(ang);
}

// ------------------------------- init cat ----------------------------------
__global__ void init_kernel(const int* __restrict__ ids,
                            const float* __restrict__ embed,
                            const float* __restrict__ beacon,
                            const float* __restrict__ forget) {
    int idx = blockIdx.x * blockDim.x + threadIdx.x;
    if (idx >= NCAT * DD) return;
    int r = idx >> 10, c = idx & 1023;
    float v;
    if (r < SS)             v = embed[(size_t)ids[r] * DD + c];
    else if (r < SS + MM)   v = beacon[(r - SS) * DD + c];
    else                    v = forget[(r - SS - MM) * DD + c];
    g_cat[idx] = v;
}

// ------------------------------ record/output ------------------------------
__global__ void record_kernel(const float* __restrict__ mem_l,
                              float* __restrict__ out_l) {
    int idx = blockIdx.x * blockDim.x + threadIdx.x;
    if (idx >= MM * DD) return;
    float b = g_cat[SS * DD + idx];
    float f = g_cat[(SS + MM) * DD + idx];
    float g = 1.f / (1.f + expf(-f));
    out_l[idx] = mem_l[idx] * g + b * (1.f - g);
}

// --------------------------------- RMSNorm ---------------------------------
__global__ __launch_bounds__(128) void rms_kernel(const float* __restrict__ in,
                                                  const float* __restrict__ w,
                                                  float* __restrict__ out) {
    const int r = blockIdx.x, tid = threadIdx.x;
    const float4* row4 = (const float4*)(in + (size_t)r * DD);
    float4 v0 = row4[tid], v1 = row4[tid + 128];
    float s = v0.x*v0.x + v0.y*v0.y + v0.z*v0.z + v0.w*v0.w
            + v1.x*v1.x + v1.y*v1.y + v1.z*v1.z + v1.w*v1.w;
#pragma unroll
    for (int o = 16; o > 0; o >>= 1) s += __shfl_down_sync(0xffffffffu, s, o);
    __shared__ float ws[4];
    if ((tid & 31) == 0) ws[tid >> 5] = s;
    __syncthreads();
    float tot = ws[0] + ws[1] + ws[2] + ws[3];
    float inv = rsqrtf(tot * (1.f / DD) + 1e-5f);
    const float4* w4 = (const float4*)w;
    float4* o4 = (float4*)(out + (size_t)r * DD);
    float4 a = w4[tid], b = w4[tid + 128];
    o4[tid]       = make_float4(v0.x*a.x*inv, v0.y*a.y*inv, v0.z*a.z*inv, v0.w*a.w*inv);
    o4[tid + 128] = make_float4(v1.x*b.x*inv, v1.y*b.y*inv, v1.z*b.z*inv, v1.w*b.w*inv);
}

// ----------------------------------- RoPE ----------------------------------
__global__ void rope_kernel(float* __restrict__ buf, int nrows, int mode) {
    int idx = blockIdx.x * blockDim.x + threadIdx.x;
    if (idx >= nrows * HH * 32) return;
    int j = idx & 31, h = (idx >> 5) & 15, r = idx >> 9;
    int pos = (mode == 0) ? ((r < 1152) ? r + 128 : r)
                          : ((r < 1280) ? r : r - 128);
    float c = g_cos[pos * 32 + j];
    float s = g_sin[pos * 32 + j];
    float* p = buf + (size_t)r * DD + h * HDIM + j;
    float x0 = p[0], x1 = p[32];
    p[0]  = x0 * c - x1 * s;
    p[32] = x1 * c + x0 * s;
}

// ------------------- pipelined batched tf32 NN GEMM ------------------------
struct GPtrs  { const float* A; const float* B; float* C; };
struct GBatch { GPtrs p[16]; };

template <int BM, int BN, int WM, int WN, bool ACC>
__global__ __launch_bounds__(256) void mma_gemm_nn(GBatch batch, int K,
                                                   int lda, int ldb, int ldc) {
    constexpr int BK = 16;
    constexpr int WARPS_N = BN / WN;
    constexpr int MT = WM / 16, NT = WN / 8;
    constexpr int ASTR = BK + 4;
    constexpr int BSTR = BN + 8;
    constexpr int AITER = (BM * BK) / (4 * 256);
    constexpr int BITER = (BK * BN) / (4 * 256);
    constexpr int BNQ = BN / 4;
    constexpr int AROWSTEP = 64;
    constexpr int BROWSTEP = 256 / BNQ;

    __shared__ float As[2][BM][ASTR];
    __shared__ float Bs[2][BK][BSTR];

    const GPtrs pr = batch.p[blockIdx.z];
    const float* __restrict__ A = pr.A;
    const float* __restrict__ B = pr.B;
    float* __restrict__ C = pr.C;
    const int bm = blockIdx.y * BM, bn = blockIdx.x * BN;
    const int tid = threadIdx.x, warp = tid >> 5, lane = tid & 31;
    const int wm = (warp / WARPS_N) * WM;
    const int wn = (warp % WARPS_N) * WN;
    const int lr = lane >> 2, lc = lane & 3;

    const int arow = tid >> 2, ac4 = (tid & 3) * 4;
    const int brow = tid / BNQ, bc4 = (tid % BNQ) * 4;

    float acc[MT][NT][4];
#pragma unroll
    for (int i = 0; i < MT; i++)
#pragma unroll
        for (int j = 0; j < NT; j++)
#pragma unroll
            for (int e = 0; e < 4; e++) acc[i][j][e] = 0.f;

    float4 ar[AITER], br[BITER];

#pragma unroll
    for (int it = 0; it < AITER; it++)
        ar[it] = *(const float4*)(A + (size_t)(bm + arow + it * AROWSTEP) * lda + ac4);
#pragma unroll
    for (int it = 0; it < BITER; it++)
        br[it] = *(const float4*)(B + (size_t)(brow + it * BROWSTEP) * ldb + bn + bc4);
#pragma unroll
    for (int it = 0; it < AITER; it++) {
        float* d = &As[0][arow + it * AROWSTEP][ac4];
        d[0] = tf32r(ar[it].x); d[1] = tf32r(ar[it].y);
        d[2] = tf32r(ar[it].z); d[3] = tf32r(ar[it].w);
    }
#pragma unroll
    for (int it = 0; it < BITER; it++) {
        float* d = &Bs[0][brow + it * BROWSTEP][bc4];
        d[0] = tf32r(br[it].x); d[1] = tf32r(br[it].y);
        d[2] = tf32r(br[it].z); d[3] = tf32r(br[it].w);
    }
    __syncthreads();

    const int nIter = K / BK;
    for (int itn = 0; itn < nIter; itn++) {
        const int buf = itn & 1;
        const bool more = (itn + 1 < nIter);
        if (more) {
            const int k0 = (itn + 1) * BK;
#pragma unroll
            for (int it = 0; it < AITER; it++)
                ar[it] = *(const float4*)(A + (size_t)(bm + arow + it * AROWSTEP) * lda + k0 + ac4);
#pragma unroll
            for (int it = 0; it < BITER; it++)
                br[it] = *(const float4*)(B + (size_t)(k0 + brow + it * BROWSTEP) * ldb + bn + bc4);
        }
#pragma unroll
        for (int kk = 0; kk < BK; kk += 8) {
            uint32_t af[MT][4], bf[NT][2];
#pragma unroll
            for (int i = 0; i < MT; i++) {
                int r = wm + i * 16 + lr;
                af[i][0] = __float_as_uint(As[buf][r    ][kk + lc    ]);
                af[i][1] = __float_as_uint(As[buf][r + 8][kk + lc    ]);
                af[i][2] = __float_as_uint(As[buf][r    ][kk + lc + 4]);
                af[i][3] = __float_as_uint(As[buf][r + 8][kk + lc + 4]);
            }
#pragma unroll
            for (int j = 0; j < NT; j++) {
                int c = wn + j * 8 + lr;
                bf[j][0] = __float_as_uint(Bs[buf][kk + lc    ][c]);
                bf[j][1] = __float_as_uint(Bs[buf][kk + lc + 4][c]);
            }
#pragma unroll
            for (int i = 0; i < MT; i++)
#pragma unroll
                for (int j = 0; j < NT; j++) mma8(acc[i][j], af[i], bf[j]);
        }
        if (more) {
            const int nb = buf ^ 1;
#pragma unroll
            for (int it = 0; it < AITER; it++) {
                float* d = &As[nb][arow + it * AROWSTEP][ac4];
                d[0] = tf32r(ar[it].x); d[1] = tf32r(ar[it].y);
                d[2] = tf32r(ar[it].z); d[3] = tf32r(ar[it].w);
            }
#pragma unroll
            for (int it = 0; it < BITER; it++) {
                float* d = &Bs[nb][brow + it * BROWSTEP][bc4];
                d[0] = tf32r(br[it].x); d[1] = tf32r(br[it].y);
                d[2] = tf32r(br[it].z); d[3] = tf32r(br[it].w);
            }
            __syncthreads();
        }
    }

#pragma unroll
    for (int i = 0; i < MT; i++)
#pragma unroll
        for (int j = 0; j < NT; j++) {
            int r = bm + wm + i * 16 + lr;
            int c = bn + wn + j * 8 + lc * 2;
            float* p0 = C + (size_t)r * ldc + c;
            float* p1 = C + (size_t)(r + 8) * ldc + c;
            if (ACC) {
                p0[0] += acc[i][j][0]; p0[1] += acc[i][j][1];
                p1[0] += acc[i][j][2]; p1[1] += acc[i][j][3];
            } else {
                p0[0] = acc[i][j][0]; p0[1] = acc[i][j][1];
                p1[0] = acc[i][j][2]; p1[1] = acc[i][j][3];
            }
        }
}

// ------------------------- fused flash attention ---------------------------
// Block: 128 thr (4 warps), 64 q-rows x 1 head. Q frags in regs, K/V tiles in
// smem, online softmax (row stats in regs), P via smem -> PV mma.
// Smem: Ks[64][68], Vs[64][72], Ps[64][68]  (pads: conflict-free frag reads)
#define KSTR 68
#define VSTR 72
__device__ __forceinline__ bool vis_mask(int r, int j) {
    return (r < 1152) ? (j <= r + 128)
                      : (j < 1152 || (j >= 1280 && j - 128 <= r));
}

__global__ __launch_bounds__(128) void fattn_kernel(const float* __restrict__ Q,
                                                    const float* __restrict__ K,
                                                    const float* __restrict__ V,
                                                    float* __restrict__ O) {
    extern __shared__ float smf[];
    float* Ks = smf;                    // [64][KSTR]
    float* Vs = smf + 64 * KSTR;        // [64][VSTR]
    float* Ps = smf + 64 * (KSTR + VSTR); // [64][KSTR]

    const int h  = blockIdx.y;
    const int bm = blockIdx.x * 64;
    const int tid = threadIdx.x, warp = tid >> 5, lane = tid & 31;
    const int lr = lane >> 2, lc = lane & 3;
    const int wm = warp * 16;
    const int r0 = bm + wm + lr, r1 = r0 + 8;

    // ---- load Q tile (via Ps as staging) then lift frags to registers ----
    for (int i = tid; i < 64 * 16; i += 128) {
        int row = i >> 4, c4 = (i & 15) * 4;
        float4 qv = *(const float4*)(Q + (size_t)(bm + row) * DD + h * HDIM + c4);
        float* d = &Ps[row * KSTR + c4];
        d[0] = tf32r(qv.x); d[1] = tf32r(qv.y); d[2] = tf32r(qv.z); d[3] = tf32r(qv.w);
    }
    __syncthreads();
    uint32_t qf[8][4];
#pragma unroll
    for (int k8 = 0; k8 < 8; k8++) {
        qf[k8][0] = __float_as_uint(Ps[(wm + lr    ) * KSTR + k8 * 8 + lc    ]);
        qf[k8][1] = __float_as_uint(Ps[(wm + lr + 8) * KSTR + k8 * 8 + lc    ]);
        qf[k8][2] = __float_as_uint(Ps[(wm + lr    ) * KSTR + k8 * 8 + lc + 4]);
        qf[k8][3] = __float_as_uint(Ps[(wm + lr + 8) * KSTR + k8 * 8 + lc + 4]);
    }
    __syncthreads();

    float m0 = -3.402823466e38f, m1 = -3.402823466e38f, s0 = 0.f, s1 = 0.f;
    float oacc[8][4];
#pragma unroll
    for (int n = 0; n < 8; n++)
#pragma unroll
        for (int e = 0; e < 4; e++) oacc[n][e] = 0.f;

    const bool fg = (bm >= SS + MM);
    const int jmax = bm + 192;   // prefix-visible bound (see R7 analysis)

    for (int j0 = 0; j0 < jmax; j0 += 64) {
        if (fg && j0 >= 1152 && j0 < 1280) continue;   // forget: key gap

        // ---- load K/V tiles ----
        for (int i = tid; i < 64 * 16; i += 128) {
            int row = i >> 4, c4 = (i & 15) * 4;
            float4 kv = *(const float4*)(K + (size_t)(j0 + row) * DD + h * HDIM + c4);
            float* dk = &Ks[row * KSTR + c4];
            dk[0] = tf32r(kv.x); dk[1] = tf32r(kv.y); dk[2] = tf32r(kv.z); dk[3] = tf32r(kv.w);
            float4 vv = *(const float4*)(V + (size_t)(j0 + row) * DD + h * HDIM + c4);
            float* dv = &Vs[row * VSTR + c4];
            dv[0] = tf32r(vv.x); dv[1] = tf32r(vv.y); dv[2] = tf32r(vv.z); dv[3] = tf32r(vv.w);
        }
        __syncthreads();

        // ---- S = Q K^T (per warp: 16 rows x 64 keys) ----
        float sacc[8][4];
#pragma unroll
        for (int n = 0; n < 8; n++)
#pragma unroll
            for (int e = 0; e < 4; e++) sacc[n][e] = 0.f;
#pragma unroll
        for (int kk = 0; kk < 64; kk += 8) {
            uint32_t bf[8][2];
#pragma unroll
            for (int n = 0; n < 8; n++) {
                bf[n][0] = __float_as_uint(Ks[(n * 8 + lr) * KSTR + kk + lc    ]);
                bf[n][1] = __float_as_uint(Ks[(n * 8 + lr) * KSTR + kk + lc + 4]);
            }
#pragma unroll
            for (int n = 0; n < 8; n++) mma8(sacc[n], qf[kk >> 3], bf[n]);
        }

        // ---- scale + mask ----
#pragma unroll
        for (int n = 0; n < 8; n++) {
            int c = j0 + n * 8 + lc * 2;
            sacc[n][0] = vis_mask(r0, c    ) ? sacc[n][0] * 0.125f : -1e30f;
            sacc[n][1] = vis_mask(r0, c + 1) ? sacc[n][1] * 0.125f : -1e30f;
            sacc[n][2] = vis_mask(r1, c    ) ? sacc[n][2] * 0.125f : -1e30f;
            sacc[n][3] = vis_mask(r1, c + 1) ? sacc[n][3] * 0.125f : -1e30f;
        }

        // ---- row max over tile (reduce over lc group: lanes lr*4+lc) ----
        float tm0 = -3.402823466e38f, tm1 = -3.402823466e38f;
#pragma unroll
        for (int n = 0; n < 8; n++) {
            tm0 = fmaxf(tm0, fmaxf(sacc[n][0], sacc[n][1]));
            tm1 = fmaxf(tm1, fmaxf(sacc[n][2], sacc[n][3]));
        }
        tm0 = fmaxf(tm0, __shfl_xor_sync(0xffffffffu, tm0, 1));
        tm0 = fmaxf(tm0, __shfl_xor_sync(0xffffffffu, tm0, 2));
        tm1 = fmaxf(tm1, __shfl_xor_sync(0xffffffffu, tm1, 1));
        tm1 = fmaxf(tm1, __shfl_xor_sync(0xffffffffu, tm1, 2));

        const float nm0 = fmaxf(m0, tm0), nm1 = fmaxf(m1, tm1);
        const float al0 = __expf(m0 - nm0), al1 = __expf(m1 - nm1);

        // ---- exp, tile sums, write P to smem ----
        float ts0 = 0.f, ts1 = 0.f;
#pragma unroll
        for (int n = 0; n < 8; n++) {
            float p0 = __expf(sacc[n][0] - nm0);
            float p1 = __expf(sacc[n][1] - nm0);
            float p2 = __expf(sacc[n][2] - nm1);
            float p3 = __expf(sacc[n][3] - nm1);
            ts0 += p0 + p1; ts1 += p2 + p3;
            float* q0 = &Ps[(wm + lr    ) * KSTR + n * 8 + lc * 2];
            float* q1 = &Ps[(wm + lr + 8) * KSTR + n * 8 + lc * 2];
            q0[0] = tf32r(p0); q0[1] = tf32r(p1);
            q1[0] = tf32r(p2); q1[1] = tf32r(p3);
        }
        ts0 += __shfl_xor_sync(0xffffffffu, ts0, 1);
        ts0 += __shfl_xor_sync(0xffffffffu, ts0, 2);
        ts1 += __shfl_xor_sync(0xffffffffu, ts1, 1);
        ts1 += __shfl_xor_sync(0xffffffffu, ts1, 2);
        s0 = s0 * al0 + ts0;  s1 = s1 * al1 + ts1;
        m0 = nm0;             m1 = nm1;

        // ---- rescale O ----
#pragma unroll
        for (int n = 0; n < 8; n++) {
            oacc[n][0] *= al0; oacc[n][1] *= al0;
            oacc[n][2] *= al1; oacc[n][3] *= al1;
        }
        __syncthreads();

        // ---- O += P V ----
#pragma unroll
        for (int kk = 0; kk < 64; kk += 8) {
            uint32_t af[4], bf[8][2];
            af[0] = __float_as_uint(Ps[(wm + lr    ) * KSTR + kk + lc    ]);
            af[1] = __float_as_uint(Ps[(wm + lr + 8) * KSTR + kk + lc    ]);
            af[2] = __float_as_uint(Ps[(wm + lr    ) * KSTR + kk + lc + 4]);
            af[3] = __float_as_uint(Ps[(wm + lr + 8) * KSTR + kk + lc + 4]);
#pragma unroll
            for (int n = 0; n < 8; n++) {
                bf[n][0] = __float_as_uint(Vs[(kk + lc    ) * VSTR + n * 8 + lr]);
                bf[n][1] = __float_as_uint(Vs[(kk + lc + 4) * VSTR + n * 8 + lr]);
            }
#pragma unroll
            for (int n = 0; n < 8; n++) mma8(oacc[n], af, bf[n]);
        }
        __syncthreads();   // protect Ks/Vs/Ps before next tile
    }

    // ---- epilogue: O /= rowsum ----
    const float i0 = 1.f / s0, i1 = 1.f / s1;
#pragma unroll
    for (int n = 0; n < 8; n++) {
        int c = h * HDIM + n * 8 + lc * 2;
        float* p0 = O + (size_t)r0 * DD + c;
        float* p1 = O + (size_t)r1 * DD + c;
        p0[0] = oacc[n][0] * i0; p0[1] = oacc[n][1] * i0;
        p1[0] = oacc[n][2] * i1; p1[1] = oacc[n][3] * i1;
    }
}

// ------------------------------ silu(g) * u --------------------------------
__global__ void silu_mul_kernel(float* __restrict__ gbuf,
                                const float* __restrict__ ubuf) {
    int idx = blockIdx.x * blockDim.x + threadIdx.x;
    if (idx >= NCAT * FF) return;
    float g = gbuf[idx];
    gbuf[idx] = g / (1.f + expf(-g)) * ubuf[idx];
}

// --------------------------------- host ------------------------------------
extern "C" void kernel_launch(void* const* d_in, const int* in_sizes, int n_in,
                              void* d_out, int out_size) {
    (void)in_sizes; (void)n_in; (void)out_size;
    const int*   ids    = (const int*)  d_in[0];
    const float* memory = (const float*)d_in[1];
    const float* beacon = (const float*)d_in[2];
    const float* forget = (const float*)d_in[3];
    const float* embed  = (const float*)d_in[4];
    const float* ln1    = (const float*)d_in[5];
    const float* ln2    = (const float*)d_in[6];
    const float* Wq     = (const float*)d_in[7];
    const float* Wk     = (const float*)d_in[8];
    const float* Wv     = (const float*)d_in[9];
    const float* Wo     = (const float*)d_in[10];
    const float* mWk    = (const float*)d_in[11];
    const float* mWv    = (const float*)d_in[12];
    const float* bWq    = (const float*)d_in[13];
    const float* bWk    = (const float*)d_in[14];
    const float* bWv    = (const float*)d_in[15];
    const float* fWq    = (const float*)d_in[16];
    const float* fWk    = (const float*)d_in[17];
    const float* fWv    = (const float*)d_in[18];
    const float* Wg     = (const float*)d_in[19];
    const float* Wu     = (const float*)d_in[20];
    const float* Wd     = (const float*)d_in[21];
    float* out = (float*)d_out;

    float *cat, *x, *q, *k, *v, *attn, *ffg, *ffu;
    cudaGetSymbolAddress((void**)&cat,  g_cat);
    cudaGetSymbolAddress((void**)&x,    g_x);
    cudaGetSymbolAddress((void**)&q,    g_q);
    cudaGetSymbolAddress((void**)&k,    g_k);
    cudaGetSymbolAddress((void**)&v,    g_v);
    cudaGetSymbolAddress((void**)&attn, g_attn);
    cudaGetSymbolAddress((void**)&ffg,  g_ffg);
    cudaGetSymbolAddress((void**)&ffu,  g_ffu);

    const int FA_SMEM = (64 * (KSTR + VSTR + KSTR)) * 4;   // ~53 KB
    cudaFuncSetAttribute(fattn_kernel,
                         cudaFuncAttributeMaxDynamicSharedMemorySize, FA_SMEM);

    rope_table_kernel<<<(NPOS * 32 + 255) / 256, 256>>>();
    init_kernel<<<(NCAT * DD + 255) / 256, 256>>>(ids, embed, beacon, forget);

    const size_t WSZ = (size_t)DD * DD;
    const size_t FSZ = (size_t)DD * FF;

    for (int l = 0; l < LL; l++) {
        const float* mem_l = memory + (size_t)l * MM * DD;
        record_kernel<<<(MM * DD + 255) / 256, 256>>>(mem_l, out + (size_t)l * MM * DD);
        if (l == LL - 1) break;   // layer 7's compute is never consumed

        const float* wq  = Wq  + (size_t)l * WSZ;
        const float* wk  = Wk  + (size_t)l * WSZ;
        const float* wv  = Wv  + (size_t)l * WSZ;
        const float* wo  = Wo  + (size_t)l * WSZ;
        const float* mwk = mWk + (size_t)l * WSZ;
        const float* mwv = mWv + (size_t)l * WSZ;
        const float* bwq = bWq + (size_t)l * WSZ;
        const float* bwk = bWk + (size_t)l * WSZ;
        const float* bwv = bWv + (size_t)l * WSZ;
        const float* fwq = fWq + (size_t)l * WSZ;
        const float* fwk = fWk + (size_t)l * WSZ;
        const float* fwv = fWv + (size_t)l * WSZ;
        const float* wg  = Wg  + (size_t)l * FSZ;
        const float* wu  = Wu  + (size_t)l * FSZ;
        const float* wd  = Wd  + (size_t)l * FSZ;

        rms_kernel<<<NCAT, 128>>>(cat, ln1 + (size_t)l * DD, x);

        {
            GBatch bb{};
            bb.p[0] = { x, wq, q };
            bb.p[1] = { x, wk, k + (size_t)MM * DD };
            bb.p[2] = { x, wv, v + (size_t)MM * DD };
            mma_gemm_nn<128,128,64,32,false><<<dim3(8,8,3), 256>>>(bb, DD, DD, DD, DD);
        }
        {
            GBatch sb{};
            sb.p[0] = { mem_l,                  mwk, k };
            sb.p[1] = { mem_l,                  mwv, v };
            sb.p[2] = { x + (size_t)SS*DD,      bwq, q + (size_t)SS*DD };
            sb.p[3] = { x + (size_t)SS*DD,      bwk, k + (size_t)(MM+SS)*DD };
            sb.p[4] = { x + (size_t)SS*DD,      bwv, v + (size_t)(MM+SS)*DD };
            sb.p[5] = { x + (size_t)(SS+MM)*DD, fwq, q + (size_t)(SS+MM)*DD };
            sb.p[6] = { x + (size_t)(SS+MM)*DD, fwk, k + (size_t)(MM+SS+MM)*DD };
            sb.p[7] = { x + (size_t)(SS+MM)*DD, fwv, v + (size_t)(MM+SS+MM)*DD };
            mma_gemm_nn<128,64,32,32,false><<<dim3(16,1,8), 256>>>(sb, DD, DD, DD, DD);
        }

        rope_kernel<<<(NCAT * HH * 32 + 255) / 256, 256>>>(q, NCAT, 0);
        rope_kernel<<<(NKR  * HH * 32 + 255) / 256, 256>>>(k, NKR,  1);

        // fused attention: 20 q-blocks x 16 heads
        fattn_kernel<<<dim3(NCAT / 64, HH), 128, FA_SMEM>>>(q, k, v, attn);

        {
            GBatch ob{};
            ob.p[0] = { attn, wo, cat };
            mma_gemm_nn<128,64,32,32,true><<<dim3(16,10,1), 256>>>(ob, DD, DD, DD, DD);
        }

        rms_kernel<<<NCAT, 128>>>(cat, ln2 + (size_t)l * DD, x);
        {
            GBatch mb{};
            mb.p[0] = { x, wg, ffg };
            mb.p[1] = { x, wu, ffu };
            mma_gemm_nn<128,128,64,32,false><<<dim3(16,10,2), 256>>>(mb, DD, DD, FF, FF);
        }
        silu_mul_kernel<<<(NCAT * FF + 255) / 256, 256>>>(ffg, ffu);
        {
            GBatch db{};
            db.p[0] = { ffg, wd, cat };
            mma_gemm_nn<128,64,32,32,true><<<dim3(16,10,1), 256>>>(db, FF, FF, DD, DD);
        }
    }
}